// round 10
// baseline (speedup 1.0000x reference)
#include <cuda_runtime.h>
#include <cuda_bf16.h>
#include <math.h>
#include <stdint.h>

// Problem dims
#define BATCH 256
#define TSTEPS 250
#define IDIM 700
#define HDIM 128
#define ODIM 20

typedef unsigned long long ull;

// xin buffer: [B][T][H] fp32 = 32.77 MB
__device__ float g_xin[BATCH * TSTEPS * HDIM];

// Correctly-rounded float exp via double (matches glibc expf). Init-path only.
__device__ __forceinline__ float expd(float x)
{
    return (float)exp((double)x);
}

#define BARSYNC(id, cnt) asm volatile("bar.sync %0, %1;" :: "r"(id), "r"(cnt) : "memory")

// Packed dual fp32 FMA: d.lo = a.lo*b.lo + c.lo ; d.hi = a.hi*b.hi + c.hi
// Each lane is an independent IEEE fp32 FMA -> bit-exact vs two fmaf.
#define FMA_F32X2(d, a, b, c) \
    asm("fma.rn.f32x2 %0, %1, %2, %3;" : "=l"(d) : "l"(a), "l"(b), "l"(c))

// ---------------------------------------------------------------------------
// Kernel 1: xin[m][h] = (sum_k x[m][k]*w[k][h]) + b[h]  (per-element single
// fp32 accumulator, strictly ascending k, bias at the end). Double-buffered
// smem; W tile stored duplicated (float2{w,w}) to feed fma.rn.f32x2 directly.
// ---------------------------------------------------------------------------
#define BM 64
#define BK 16

__global__ __launch_bounds__(256) void gemm_xin_kernel(
    const float* __restrict__ X, const float* __restrict__ W,
    const float* __restrict__ bias)
{
    __shared__ float  Xs[2][BK][BM];          // 2 x 4KB
    __shared__ float2 Wd[2][BK][HDIM];        // 2 x 16KB, duplicated pairs

    const int tid = threadIdx.x;
    const int m0 = blockIdx.x * BM;

    const int ty = tid >> 5;        // 0..7
    const int tx = tid & 31;        // 0..31
    const int mBase = ty * 8;       // 8 rows per thread (4 packed pairs)
    const int nBase = tx * 4;       // 4 cols per thread

    ull acc2[4][4];                 // [m-pair][n] packed fp32x2
#pragma unroll
    for (int p = 0; p < 4; p++)
#pragma unroll
        for (int j = 0; j < 4; j++) acc2[p][j] = 0ull;

    const int lr = tid >> 2;          // 0..63 (X tile row)
    const int lc = (tid & 3) * 4;     // X tile k chunk
    const int wr = tid >> 5;          // 0..7 (W tile row)
    const int wc = (tid & 31) * 4;    // W tile col chunk

    const int NT = (IDIM + BK - 1) / BK;   // 44

    // prologue: tile 0
#pragma unroll
    for (int i = 0; i < 4; i++) {
        int k = lc + i;
        Xs[0][lc + i][lr] = (k < IDIM) ? X[(size_t)(m0 + lr) * IDIM + k] : 0.f;
    }
#pragma unroll
    for (int rr = 0; rr < 2; rr++) {
        int k = wr + rr * 8;
        float4 v = make_float4(0.f, 0.f, 0.f, 0.f);
        if (k < IDIM) v = *(const float4*)&W[(size_t)k * HDIM + wc];
        Wd[0][wr + rr * 8][wc + 0] = make_float2(v.x, v.x);
        Wd[0][wr + rr * 8][wc + 1] = make_float2(v.y, v.y);
        Wd[0][wr + rr * 8][wc + 2] = make_float2(v.z, v.z);
        Wd[0][wr + rr * 8][wc + 3] = make_float2(v.w, v.w);
    }
    __syncthreads();

    int buf = 0;
    for (int kt = 0; kt < NT; kt++) {
        const bool has_next = (kt + 1) < NT;
        const int k0n = (kt + 1) * BK;

        float xr[4];
        float4 wv[2];
        if (has_next) {
#pragma unroll
            for (int i = 0; i < 4; i++) {
                int k = k0n + lc + i;
                xr[i] = (k < IDIM) ? X[(size_t)(m0 + lr) * IDIM + k] : 0.f;
            }
#pragma unroll
            for (int rr = 0; rr < 2; rr++) {
                int k = k0n + wr + rr * 8;
                wv[rr] = make_float4(0.f, 0.f, 0.f, 0.f);
                if (k < IDIM) wv[rr] = *(const float4*)&W[(size_t)k * HDIM + wc];
            }
        }

        // compute (strictly ascending k; each acc lane = one output element)
#pragma unroll
        for (int k = 0; k < BK; k++) {
            ull xp[4];
#pragma unroll
            for (int p = 0; p < 4; p++)
                xp[p] = *(const ull*)&Xs[buf][k][mBase + 2 * p];  // broadcast
            ull wd[4];
#pragma unroll
            for (int j = 0; j < 4; j++)
                wd[j] = *(const ull*)&Wd[buf][k][nBase + j];
#pragma unroll
            for (int p = 0; p < 4; p++)
#pragma unroll
                for (int j = 0; j < 4; j++)
                    FMA_F32X2(acc2[p][j], xp[p], wd[j], acc2[p][j]);
        }

        if (has_next) {
            int nb = buf ^ 1;
#pragma unroll
            for (int i = 0; i < 4; i++) Xs[nb][lc + i][lr] = xr[i];
#pragma unroll
            for (int rr = 0; rr < 2; rr++) {
                Wd[nb][wr + rr * 8][wc + 0] = make_float2(wv[rr].x, wv[rr].x);
                Wd[nb][wr + rr * 8][wc + 1] = make_float2(wv[rr].y, wv[rr].y);
                Wd[nb][wr + rr * 8][wc + 2] = make_float2(wv[rr].z, wv[rr].z);
                Wd[nb][wr + rr * 8][wc + 3] = make_float2(wv[rr].w, wv[rr].w);
            }
            __syncthreads();
            buf = nb;
        }
    }

    float4 bb = *(const float4*)&bias[nBase];
#pragma unroll
    for (int p = 0; p < 4; p++) {
        float lo[4], hi[4];
#pragma unroll
        for (int j = 0; j < 4; j++)
            asm("mov.b64 {%0, %1}, %2;" : "=f"(lo[j]), "=f"(hi[j]) : "l"(acc2[p][j]));
        float4 r0, r1;
        r0.x = __fadd_rn(lo[0], bb.x); r0.y = __fadd_rn(lo[1], bb.y);
        r0.z = __fadd_rn(lo[2], bb.z); r0.w = __fadd_rn(lo[3], bb.w);
        r1.x = __fadd_rn(hi[0], bb.x); r1.y = __fadd_rn(hi[1], bb.y);
        r1.z = __fadd_rn(hi[2], bb.z); r1.w = __fadd_rn(hi[3], bb.w);
        *(float4*)&g_xin[(size_t)(m0 + mBase + 2 * p + 0) * HDIM + nBase] = r0;
        *(float4*)&g_xin[(size_t)(m0 + mBase + 2 * p + 1) * HDIM + nBase] = r1;
    }
}

// ---------------------------------------------------------------------------
// Kernel 2: A_norm
// ---------------------------------------------------------------------------
__global__ void anorm_kernel(const float* __restrict__ w11,
                             const float* __restrict__ w22,
                             const float* __restrict__ mask,
                             float* __restrict__ out)
{
    __shared__ float redA[256];
    __shared__ float redB[256];
    int tid = threadIdx.x;
    float sa = 0.f, sb = 0.f;
    for (int i = tid; i < HDIM * HDIM; i += 256) {
        sa += fabsf(__fmul_rn(w11[i], mask[i]));
        sb += fabsf(__fmul_rn(w22[i], mask[HDIM * HDIM + i]));
    }
    redA[tid] = sa;
    redB[tid] = sb;
    __syncthreads();
    for (int o = 128; o > 0; o >>= 1) {
        if (tid < o) { redA[tid] += redA[tid + o]; redB[tid] += redB[tid + o]; }
        __syncthreads();
    }
    if (tid == 0)
        out[BATCH * ODIM + 2 * BATCH * HDIM] = __fadd_rn(redA[0], redB[0]);
}

// ---------------------------------------------------------------------------
// Kernel 3: persistent scan. grid = 128 blocks x 192 threads.
// Warps 0-3: neuron compute (thread = h, 2 batch rows). Warps 4-5: pipelined
// readout one step behind on the double-buffered s2 arrays.
// Weights stored TRANSPOSED + padded (wT[h*133.. 132 + j]) so each thread
// reads its column with float4 LDS (conflict-free, 4x fewer LDS instrs).
// ---------------------------------------------------------------------------
#define WSTRIDE 132   // 128 + 4 pad: phase-conflict-free float4 column reads

__device__ __forceinline__ void dot_pairT(const float* __restrict__ WT,
                                          const float* __restrict__ sa,
                                          const float* __restrict__ sb,
                                          float& a0, float& a1)
{
#pragma unroll 8
    for (int j = 0; j < HDIM; j += 4) {
        float4 w4 = *(const float4*)(WT + j);
        float4 va = *(const float4*)(sa + j);
        float4 vb = *(const float4*)(sb + j);
        a0 = fmaf(va.x, w4.x, a0); a1 = fmaf(vb.x, w4.x, a1);
        a0 = fmaf(va.y, w4.y, a0); a1 = fmaf(vb.y, w4.y, a1);
        a0 = fmaf(va.z, w4.z, a0); a1 = fmaf(vb.z, w4.z, a1);
        a0 = fmaf(va.w, w4.w, a0); a1 = fmaf(vb.w, w4.w, a1);
    }
}

#define SM_W11 0
#define SM_W12 (HDIM * WSTRIDE)
#define SM_W22 (2 * HDIM * WSTRIDE)
#define SM_W2O (3 * HDIM * WSTRIDE)
#define SM_S1  (3 * HDIM * WSTRIDE + HDIM * ODIM)   // [2 phase][2 row][128]
#define SM_S2  (SM_S1 + 4 * HDIM)
#define SMEM_FLOATS (SM_S2 + 4 * HDIM)

#define NTHREADS_SCAN 192

__global__ __launch_bounds__(NTHREADS_SCAN) void scan_kernel(
    const float* __restrict__ mask,
    const float* __restrict__ w_h1h1, const float* __restrict__ b_h1h1,
    const float* __restrict__ w_h1h2, const float* __restrict__ b_h1h2,
    const float* __restrict__ w_h2h2, const float* __restrict__ b_h2h2,
    const float* __restrict__ w_h2o,  const float* __restrict__ b_h2o,
    const float* __restrict__ tau_adp_h1, const float* __restrict__ tau_adp_h2,
    const float* __restrict__ tau_m_h1,   const float* __restrict__ tau_m_h2,
    const float* __restrict__ tau_m_o,
    const float* __restrict__ hid1_mem0, const float* __restrict__ hid2_mem0,
    const float* __restrict__ out_mem0,
    float* __restrict__ out)
{
    extern __shared__ float sm[];
    float* w11 = sm + SM_W11;   // transposed [h][j], stride WSTRIDE
    float* w12 = sm + SM_W12;
    float* w22 = sm + SM_W22;
    float* w2o = sm + SM_W2O;   // [j][o] as in input
    float* s1b = sm + SM_S1;    // [phase][row][128]
    float* s2b = sm + SM_S2;

    const int tid = threadIdx.x;
    const int r0 = blockIdx.x * 2;
    const int r1 = r0 + 1;

    // transpose weights into smem: wT[h*WSTRIDE + j] = w[j*128 + h] (* mask)
    for (int idx = tid; idx < HDIM * HDIM; idx += NTHREADS_SCAN) {
        int j = idx >> 7, hh = idx & 127;          // coalesced gmem read
        w11[hh * WSTRIDE + j] = __fmul_rn(w_h1h1[idx], mask[idx]);
        w12[hh * WSTRIDE + j] = w_h1h2[idx];
        w22[hh * WSTRIDE + j] = __fmul_rn(w_h2h2[idx], mask[HDIM * HDIM + idx]);
    }
    for (int idx = tid; idx < HDIM * ODIM; idx += NTHREADS_SCAN)
        w2o[idx] = w_h2o[idx];

    if (tid < 128) {
        // ================= compute warps (0-3) =================
        const int h = tid;
        const float* wt11 = w11 + h * WSTRIDE;
        const float* wt12 = w12 + h * WSTRIDE;
        const float* wt22 = w22 + h * WSTRIDE;

        const float a1  = expd(__fdiv_rn(-1.0f, tau_m_h1[h]));
        const float r1d = expd(__fdiv_rn(-1.0f, tau_adp_h1[h]));
        const float a2  = expd(__fdiv_rn(-1.0f, tau_m_h2[h]));
        const float r2d = expd(__fdiv_rn(-1.0f, tau_adp_h2[h]));
        const float om_a1  = __fsub_rn(1.0f, a1);
        const float om_r1d = __fsub_rn(1.0f, r1d);
        const float om_a2  = __fsub_rn(1.0f, a2);
        const float om_r2d = __fsub_rn(1.0f, r2d);
        const float bh11 = b_h1h1[h];
        const float b12  = b_h1h2[h];
        const float b22c = b_h2h2[h];

        float h1m0 = hid1_mem0[r0 * HDIM + h], h1m1 = hid1_mem0[r1 * HDIM + h];
        float h2m0 = hid2_mem0[r0 * HDIM + h], h2m1 = hid2_mem0[r1 * HDIM + h];
        float b1_0 = 0.01f, b1_1 = 0.01f, b2_0 = 0.01f, b2_1 = 0.01f;
        float s1reg0 = 0.f, s1reg1 = 0.f, s2reg0 = 0.f, s2reg1 = 0.f;
        float s1c0 = 0.f, s1c1 = 0.f, s2c0 = 0.f, s2c1 = 0.f;

        // zero phase-0 spike buffers (read at t=0)
        s1b[h] = 0.f; s1b[HDIM + h] = 0.f;
        s2b[h] = 0.f; s2b[HDIM + h] = 0.f;

        __syncthreads();

        float xt0 = g_xin[((size_t)r0 * TSTEPS + 0) * HDIM + h];
        float xt1 = g_xin[((size_t)r1 * TSTEPS + 0) * HDIM + h];

        for (int t = 0; t < TSTEPS; t++) {
            const int rd = (t & 1) * 2 * HDIM;
            const int wr = ((t & 1) ^ 1) * 2 * HDIM;

            // ---- layer 1 ----
            float d11_0 = 0.f, d11_1 = 0.f;
            dot_pairT(wt11, s1b + rd, s1b + rd + HDIM, d11_0, d11_1);
            float i10 = __fadd_rn(__fadd_rn(xt0, d11_0), bh11);
            float i11 = __fadd_rn(__fadd_rn(xt1, d11_1), bh11);
            if (t < TSTEPS - 1) {
                xt0 = g_xin[((size_t)r0 * TSTEPS + t + 1) * HDIM + h];
                xt1 = g_xin[((size_t)r1 * TSTEPS + t + 1) * HDIM + h];
            }

            b1_0 = __fadd_rn(__fmul_rn(r1d, b1_0), __fmul_rn(om_r1d, s1reg0));
            b1_1 = __fadd_rn(__fmul_rn(r1d, b1_1), __fmul_rn(om_r1d, s1reg1));
            float B10 = __fadd_rn(0.01f, __fmul_rn(1.8f, b1_0));
            float B11 = __fadd_rn(0.01f, __fmul_rn(1.8f, b1_1));
            h1m0 = __fsub_rn(__fadd_rn(__fmul_rn(h1m0, a1), __fmul_rn(om_a1, i10)),
                             __fmul_rn(B10, s1reg0));
            h1m1 = __fsub_rn(__fadd_rn(__fmul_rn(h1m1, a1), __fmul_rn(om_a1, i11)),
                             __fmul_rn(B11, s1reg1));
            float ns0 = __fsub_rn(h1m0, B10) > 0.f ? 1.f : 0.f;
            float ns1 = __fsub_rn(h1m1, B11) > 0.f ? 1.f : 0.f;
            s1c0 += ns0; s1c1 += ns1;

            s1b[wr + h] = ns0; s1b[wr + HDIM + h] = ns1;
            s1reg0 = ns0; s1reg1 = ns1;
            BARSYNC(1, 128);                     // new s1 visible (compute only)

            // ---- layer 2 ----
            float d12_0 = 0.f, d12_1 = 0.f;
            dot_pairT(wt12, s1b + wr, s1b + wr + HDIM, d12_0, d12_1);
            float d22_0 = 0.f, d22_1 = 0.f;
            dot_pairT(wt22, s2b + rd, s2b + rd + HDIM, d22_0, d22_1);
            float i20 = __fadd_rn(__fadd_rn(__fadd_rn(d12_0, b12), d22_0), b22c);
            float i21 = __fadd_rn(__fadd_rn(__fadd_rn(d12_1, b12), d22_1), b22c);

            b2_0 = __fadd_rn(__fmul_rn(r2d, b2_0), __fmul_rn(om_r2d, s2reg0));
            b2_1 = __fadd_rn(__fmul_rn(r2d, b2_1), __fmul_rn(om_r2d, s2reg1));
            float B20 = __fadd_rn(0.01f, __fmul_rn(1.8f, b2_0));
            float B21 = __fadd_rn(0.01f, __fmul_rn(1.8f, b2_1));
            h2m0 = __fsub_rn(__fadd_rn(__fmul_rn(h2m0, a2), __fmul_rn(om_a2, i20)),
                             __fmul_rn(B20, s2reg0));
            h2m1 = __fsub_rn(__fadd_rn(__fmul_rn(h2m1, a2), __fmul_rn(om_a2, i21)),
                             __fmul_rn(B21, s2reg1));
            float ms0 = __fsub_rn(h2m0, B20) > 0.f ? 1.f : 0.f;
            float ms1 = __fsub_rn(h2m1, B21) > 0.f ? 1.f : 0.f;
            s2c0 += ms0; s2c1 += ms1;

            s2b[wr + h] = ms0; s2b[wr + HDIM + h] = ms1;
            s2reg0 = ms0; s2reg1 = ms1;
            BARSYNC(2, 192);                     // step end: hand s2 to readout
        }

        out[BATCH * ODIM + r0 * HDIM + h] = __fdiv_rn(s1c0, (float)TSTEPS);
        out[BATCH * ODIM + r1 * HDIM + h] = __fdiv_rn(s1c1, (float)TSTEPS);
        out[BATCH * ODIM + BATCH * HDIM + r0 * HDIM + h] = __fdiv_rn(s2c0, (float)TSTEPS);
        out[BATCH * ODIM + BATCH * HDIM + r1 * HDIM + h] = __fdiv_rn(s2c1, (float)TSTEPS);
    } else {
        // ================= readout warps (4-5), one per row =================
        const int lane = tid & 31;
        const int row  = (tid >> 5) - 4;         // 0 or 1

        float om = 0.f, accv = 0.f, ao = 0.f, om_ao = 0.f, b2o = 0.f;
        if (lane < ODIM) {
            om    = out_mem0[(r0 + row) * ODIM + lane];
            ao    = expd(__fdiv_rn(-1.0f, tau_m_o[lane]));
            om_ao = __fsub_rn(1.0f, ao);
            b2o   = b_h2o[lane];
        }
        __syncthreads();

        for (int t = 0; t < TSTEPS; t++) {
            BARSYNC(2, 192);                     // s2 of step t is ready
            const int wr = ((t & 1) ^ 1) * 2 * HDIM;
            const float* ss = s2b + wr + row * HDIM;

            if (lane < ODIM) {
                float dio = 0.f;                 // ascending j, single acc
#pragma unroll 4
                for (int j = 0; j < HDIM; j++)
                    dio = fmaf(ss[j], w2o[j * ODIM + lane], dio);
                float io = __fadd_rn(dio, b2o);
                om = __fadd_rn(__fmul_rn(om, ao), __fmul_rn(om_ao, io));
            }
            // softmax over 20 logits: tree max (exact) + tree sum + expf
            // (feeds only output 0; ulp-level noise, no trajectory feedback)
            float v = (lane < ODIM) ? om : -3.4e38f;
#pragma unroll
            for (int off = 16; off > 0; off >>= 1)
                v = fmaxf(v, __shfl_xor_sync(0xffffffffu, v, off));
            float p = (lane < ODIM) ? expf(__fsub_rn(om, v)) : 0.f;
            float ssum = p;
#pragma unroll
            for (int off = 16; off > 0; off >>= 1)
                ssum = __fadd_rn(ssum, __shfl_xor_sync(0xffffffffu, ssum, off));
            if (lane < ODIM && t > 10)
                accv = __fadd_rn(accv, __fdiv_rn(p, ssum));
        }

        if (lane < ODIM)
            out[(r0 + row) * ODIM + lane] = accv;
    }
}

// ---------------------------------------------------------------------------
extern "C" void kernel_launch(void* const* d_in, const int* in_sizes, int n_in,
                              void* d_out, int out_size)
{
    const float* x         = (const float*)d_in[0];
    const float* mask      = (const float*)d_in[1];
    const float* w_ih1     = (const float*)d_in[2];
    const float* b_ih1     = (const float*)d_in[3];
    const float* w_h1h1    = (const float*)d_in[4];
    const float* b_h1h1    = (const float*)d_in[5];
    const float* w_h1h2    = (const float*)d_in[6];
    const float* b_h1h2    = (const float*)d_in[7];
    const float* w_h2h2    = (const float*)d_in[8];
    const float* b_h2h2    = (const float*)d_in[9];
    const float* w_h2o     = (const float*)d_in[10];
    const float* b_h2o     = (const float*)d_in[11];
    const float* tau_adp_h1= (const float*)d_in[12];
    const float* tau_adp_h2= (const float*)d_in[13];
    const float* tau_m_h1  = (const float*)d_in[14];
    const float* tau_m_h2  = (const float*)d_in[15];
    const float* tau_m_o   = (const float*)d_in[16];
    const float* hid1_mem0 = (const float*)d_in[17];
    const float* hid2_mem0 = (const float*)d_in[18];
    const float* out_mem0  = (const float*)d_in[19];
    float* out = (float*)d_out;

    gemm_xin_kernel<<<(BATCH * TSTEPS) / BM, 256>>>(x, w_ih1, b_ih1);

    anorm_kernel<<<1, 256>>>(w_h1h1, w_h2h2, mask, out);

    size_t smem = SMEM_FLOATS * sizeof(float);
    cudaFuncSetAttribute(scan_kernel,
                         cudaFuncAttributeMaxDynamicSharedMemorySize,
                         (int)smem);
    scan_kernel<<<BATCH / 2, NTHREADS_SCAN, smem>>>(
        mask, w_h1h1, b_h1h1, w_h1h2, b_h1h2, w_h2h2, b_h2h2,
        w_h2o, b_h2o, tau_adp_h1, tau_adp_h2, tau_m_h1, tau_m_h2,
        tau_m_o, hid1_mem0, hid2_mem0, out_mem0, out);
}

// round 11
// speedup vs baseline: 1.6600x; 1.6600x over previous
#include <cuda_runtime.h>
#include <cuda_bf16.h>
#include <math.h>
#include <stdint.h>

// Problem dims
#define BATCH 256
#define TSTEPS 250
#define IDIM 700
#define HDIM 128
#define ODIM 20

// xin buffer: [B][T][H] fp32 = 32.77 MB
__device__ float g_xin[BATCH * TSTEPS * HDIM];

// Correctly-rounded float exp via double (matches glibc expf). Init-path only.
__device__ __forceinline__ float expd(float x)
{
    return (float)exp((double)x);
}

#define BARSYNC(id, cnt) asm volatile("bar.sync %0, %1;" :: "r"(id), "r"(cnt) : "memory")

// ---------------------------------------------------------------------------
// Kernel 1 (exact R9 version, 305us known-good): xin[m][h] =
// (sum_k x[m][k]*w[k][h]) + b[h], single fp32 acc, ascending k, bias last.
// Double-buffered smem pipeline.
// ---------------------------------------------------------------------------
#define BM 64
#define BK 16

__global__ __launch_bounds__(256) void gemm_xin_kernel(
    const float* __restrict__ X, const float* __restrict__ W,
    const float* __restrict__ bias)
{
    __shared__ float Xs[2][BK][BM];
    __shared__ float Ws[2][BK][HDIM];

    const int tid = threadIdx.x;
    const int m0 = blockIdx.x * BM;

    const int ty = tid >> 5;        // 0..7
    const int tx = tid & 31;        // 0..31
    const int mBase = ty * 8;       // 8 rows per thread
    const int nBase = tx * 4;       // 4 cols per thread

    float acc[8][4];
#pragma unroll
    for (int i = 0; i < 8; i++)
#pragma unroll
        for (int j = 0; j < 4; j++) acc[i][j] = 0.f;

    const int lr = tid >> 2;          // 0..63 (X tile row)
    const int lc = (tid & 3) * 4;     // X tile k chunk
    const int wr = tid >> 5;          // 0..7 (W tile row)
    const int wc = (tid & 31) * 4;    // W tile col chunk

    const int NT = (IDIM + BK - 1) / BK;   // 44

#pragma unroll
    for (int i = 0; i < 4; i++) {
        int k = lc + i;
        Xs[0][lc + i][lr] = (k < IDIM) ? X[(size_t)(m0 + lr) * IDIM + k] : 0.f;
    }
#pragma unroll
    for (int rr = 0; rr < 2; rr++) {
        int k = wr + rr * 8;
        float4 v = make_float4(0.f, 0.f, 0.f, 0.f);
        if (k < IDIM) v = *(const float4*)&W[(size_t)k * HDIM + wc];
        *(float4*)&Ws[0][wr + rr * 8][wc] = v;
    }
    __syncthreads();

    int buf = 0;
    for (int kt = 0; kt < NT; kt++) {
        const bool has_next = (kt + 1) < NT;
        const int k0n = (kt + 1) * BK;

        float xr[4];
        float4 wv[2];
        if (has_next) {
#pragma unroll
            for (int i = 0; i < 4; i++) {
                int k = k0n + lc + i;
                xr[i] = (k < IDIM) ? X[(size_t)(m0 + lr) * IDIM + k] : 0.f;
            }
#pragma unroll
            for (int rr = 0; rr < 2; rr++) {
                int k = k0n + wr + rr * 8;
                wv[rr] = make_float4(0.f, 0.f, 0.f, 0.f);
                if (k < IDIM) wv[rr] = *(const float4*)&W[(size_t)k * HDIM + wc];
            }
        }

#pragma unroll
        for (int k = 0; k < BK; k++) {   // strictly ascending k
            float4 x0 = *(float4*)&Xs[buf][k][mBase];
            float4 x1 = *(float4*)&Xs[buf][k][mBase + 4];
            float4 w4 = *(float4*)&Ws[buf][k][nBase];
            float xv[8] = {x0.x, x0.y, x0.z, x0.w, x1.x, x1.y, x1.z, x1.w};
            float wvv[4] = {w4.x, w4.y, w4.z, w4.w};
#pragma unroll
            for (int i = 0; i < 8; i++)
#pragma unroll
                for (int j = 0; j < 4; j++)
                    acc[i][j] = fmaf(xv[i], wvv[j], acc[i][j]);
        }

        if (has_next) {
            int nb = buf ^ 1;
#pragma unroll
            for (int i = 0; i < 4; i++) Xs[nb][lc + i][lr] = xr[i];
#pragma unroll
            for (int rr = 0; rr < 2; rr++)
                *(float4*)&Ws[nb][wr + rr * 8][wc] = wv[rr];
            __syncthreads();
            buf = nb;
        }
    }

    float4 bb = *(const float4*)&bias[nBase];
#pragma unroll
    for (int i = 0; i < 8; i++) {
        float4 r;
        r.x = __fadd_rn(acc[i][0], bb.x);
        r.y = __fadd_rn(acc[i][1], bb.y);
        r.z = __fadd_rn(acc[i][2], bb.z);
        r.w = __fadd_rn(acc[i][3], bb.w);
        *(float4*)&g_xin[(size_t)(m0 + mBase + i) * HDIM + nBase] = r;
    }
}

// ---------------------------------------------------------------------------
// Kernel 2: A_norm
// ---------------------------------------------------------------------------
__global__ void anorm_kernel(const float* __restrict__ w11,
                             const float* __restrict__ w22,
                             const float* __restrict__ mask,
                             float* __restrict__ out)
{
    __shared__ float redA[256];
    __shared__ float redB[256];
    int tid = threadIdx.x;
    float sa = 0.f, sb = 0.f;
    for (int i = tid; i < HDIM * HDIM; i += 256) {
        sa += fabsf(__fmul_rn(w11[i], mask[i]));
        sb += fabsf(__fmul_rn(w22[i], mask[HDIM * HDIM + i]));
    }
    redA[tid] = sa;
    redB[tid] = sb;
    __syncthreads();
    for (int o = 128; o > 0; o >>= 1) {
        if (tid < o) { redA[tid] += redA[tid + o]; redB[tid] += redB[tid + o]; }
        __syncthreads();
    }
    if (tid == 0)
        out[BATCH * ODIM + 2 * BATCH * HDIM] = __fadd_rn(redA[0], redB[0]);
}

// ---------------------------------------------------------------------------
// Kernel 3: persistent scan. grid = 128 blocks x 192 threads.
// Warps 0-3: neuron compute (thread = h, 2 batch rows, R9 weight layout
// w[j*128+h], coalesced scalar LDS). Warps 4-5: pipelined readout 1 step
// behind on the double-buffered s2 arrays.
// NEW: dot11+dot22 fused into ONE fully-unrolled loop (both read OLD spikes;
// 4 independent ascending-j chains -> bit-exact, latency-hiding ILP), and
// dot12 fully unrolled. Everything else identical to R9.
// ---------------------------------------------------------------------------

// fused dual-matrix dot: a += WA^T s1 (rows a0,a1), c += WB^T s2 (rows c0,c1)
__device__ __forceinline__ void dot_quad(const float* __restrict__ WA,
                                         const float* __restrict__ WB,
                                         const float* __restrict__ s1a,
                                         const float* __restrict__ s1bb,
                                         const float* __restrict__ s2a,
                                         const float* __restrict__ s2bb,
                                         int h,
                                         float& a0, float& a1,
                                         float& c0, float& c1)
{
#pragma unroll
    for (int j = 0; j < HDIM; j += 4) {
        float4 va = *(const float4*)(s1a + j);
        float4 vb = *(const float4*)(s1bb + j);
        float4 ua = *(const float4*)(s2a + j);
        float4 ub = *(const float4*)(s2bb + j);
        float wa0 = WA[(j + 0) * HDIM + h];
        float wa1 = WA[(j + 1) * HDIM + h];
        float wa2 = WA[(j + 2) * HDIM + h];
        float wa3 = WA[(j + 3) * HDIM + h];
        float wb0 = WB[(j + 0) * HDIM + h];
        float wb1 = WB[(j + 1) * HDIM + h];
        float wb2 = WB[(j + 2) * HDIM + h];
        float wb3 = WB[(j + 3) * HDIM + h];
        a0 = fmaf(va.x, wa0, a0); a1 = fmaf(vb.x, wa0, a1);
        c0 = fmaf(ua.x, wb0, c0); c1 = fmaf(ub.x, wb0, c1);
        a0 = fmaf(va.y, wa1, a0); a1 = fmaf(vb.y, wa1, a1);
        c0 = fmaf(ua.y, wb1, c0); c1 = fmaf(ub.y, wb1, c1);
        a0 = fmaf(va.z, wa2, a0); a1 = fmaf(vb.z, wa2, a1);
        c0 = fmaf(ua.z, wb2, c0); c1 = fmaf(ub.z, wb2, c1);
        a0 = fmaf(va.w, wa3, a0); a1 = fmaf(vb.w, wa3, a1);
        c0 = fmaf(ua.w, wb3, c0); c1 = fmaf(ub.w, wb3, c1);
    }
}

__device__ __forceinline__ void dot_pair(const float* __restrict__ W,
                                         const float* __restrict__ sa,
                                         const float* __restrict__ sb,
                                         int h, float& a0, float& a1)
{
#pragma unroll
    for (int j = 0; j < HDIM; j += 4) {
        float4 va = *(const float4*)(sa + j);
        float4 vb = *(const float4*)(sb + j);
        float w0 = W[(j + 0) * HDIM + h];
        float w1 = W[(j + 1) * HDIM + h];
        float w2 = W[(j + 2) * HDIM + h];
        float w3 = W[(j + 3) * HDIM + h];
        a0 = fmaf(va.x, w0, a0); a1 = fmaf(vb.x, w0, a1);
        a0 = fmaf(va.y, w1, a0); a1 = fmaf(vb.y, w1, a1);
        a0 = fmaf(va.z, w2, a0); a1 = fmaf(vb.z, w2, a1);
        a0 = fmaf(va.w, w3, a0); a1 = fmaf(vb.w, w3, a1);
    }
}

#define SM_W11 0
#define SM_W12 (HDIM * HDIM)
#define SM_W22 (2 * HDIM * HDIM)
#define SM_W2O (3 * HDIM * HDIM)
#define SM_S1  (3 * HDIM * HDIM + HDIM * ODIM)   // [2 phase][2 row][128]
#define SM_S2  (SM_S1 + 4 * HDIM)
#define SMEM_FLOATS (SM_S2 + 4 * HDIM)

#define NTHREADS_SCAN 192

__global__ __launch_bounds__(NTHREADS_SCAN) void scan_kernel(
    const float* __restrict__ mask,
    const float* __restrict__ w_h1h1, const float* __restrict__ b_h1h1,
    const float* __restrict__ w_h1h2, const float* __restrict__ b_h1h2,
    const float* __restrict__ w_h2h2, const float* __restrict__ b_h2h2,
    const float* __restrict__ w_h2o,  const float* __restrict__ b_h2o,
    const float* __restrict__ tau_adp_h1, const float* __restrict__ tau_adp_h2,
    const float* __restrict__ tau_m_h1,   const float* __restrict__ tau_m_h2,
    const float* __restrict__ tau_m_o,
    const float* __restrict__ hid1_mem0, const float* __restrict__ hid2_mem0,
    const float* __restrict__ out_mem0,
    float* __restrict__ out)
{
    extern __shared__ float sm[];
    float* w11 = sm + SM_W11;   // [j][h] as input (coalesced column reads)
    float* w12 = sm + SM_W12;
    float* w22 = sm + SM_W22;
    float* w2o = sm + SM_W2O;
    float* s1b = sm + SM_S1;    // [phase][row][128]
    float* s2b = sm + SM_S2;

    const int tid = threadIdx.x;
    const int r0 = blockIdx.x * 2;
    const int r1 = r0 + 1;

    for (int idx = tid; idx < HDIM * HDIM; idx += NTHREADS_SCAN) {
        w11[idx] = __fmul_rn(w_h1h1[idx], mask[idx]);
        w12[idx] = w_h1h2[idx];
        w22[idx] = __fmul_rn(w_h2h2[idx], mask[HDIM * HDIM + idx]);
    }
    for (int idx = tid; idx < HDIM * ODIM; idx += NTHREADS_SCAN)
        w2o[idx] = w_h2o[idx];

    if (tid < 128) {
        // ================= compute warps (0-3) =================
        const int h = tid;

        const float a1  = expd(__fdiv_rn(-1.0f, tau_m_h1[h]));
        const float r1d = expd(__fdiv_rn(-1.0f, tau_adp_h1[h]));
        const float a2  = expd(__fdiv_rn(-1.0f, tau_m_h2[h]));
        const float r2d = expd(__fdiv_rn(-1.0f, tau_adp_h2[h]));
        const float om_a1  = __fsub_rn(1.0f, a1);
        const float om_r1d = __fsub_rn(1.0f, r1d);
        const float om_a2  = __fsub_rn(1.0f, a2);
        const float om_r2d = __fsub_rn(1.0f, r2d);
        const float bh11 = b_h1h1[h];
        const float b12  = b_h1h2[h];
        const float b22c = b_h2h2[h];

        float h1m0 = hid1_mem0[r0 * HDIM + h], h1m1 = hid1_mem0[r1 * HDIM + h];
        float h2m0 = hid2_mem0[r0 * HDIM + h], h2m1 = hid2_mem0[r1 * HDIM + h];
        float b1_0 = 0.01f, b1_1 = 0.01f, b2_0 = 0.01f, b2_1 = 0.01f;
        float s1reg0 = 0.f, s1reg1 = 0.f, s2reg0 = 0.f, s2reg1 = 0.f;
        float s1c0 = 0.f, s1c1 = 0.f, s2c0 = 0.f, s2c1 = 0.f;

        // zero phase-0 spike buffers (read at t=0)
        s1b[h] = 0.f; s1b[HDIM + h] = 0.f;
        s2b[h] = 0.f; s2b[HDIM + h] = 0.f;

        __syncthreads();

        float xt0 = g_xin[((size_t)r0 * TSTEPS + 0) * HDIM + h];
        float xt1 = g_xin[((size_t)r1 * TSTEPS + 0) * HDIM + h];

        for (int t = 0; t < TSTEPS; t++) {
            const int rd = (t & 1) * 2 * HDIM;
            const int wr = ((t & 1) ^ 1) * 2 * HDIM;

            // ---- fused dot11 (old s1) + dot22 (old s2): 4 chains ----
            float d11_0 = 0.f, d11_1 = 0.f, d22_0 = 0.f, d22_1 = 0.f;
            dot_quad(w11, w22,
                     s1b + rd, s1b + rd + HDIM,
                     s2b + rd, s2b + rd + HDIM,
                     h, d11_0, d11_1, d22_0, d22_1);

            float i10 = __fadd_rn(__fadd_rn(xt0, d11_0), bh11);
            float i11 = __fadd_rn(__fadd_rn(xt1, d11_1), bh11);
            if (t < TSTEPS - 1) {
                xt0 = g_xin[((size_t)r0 * TSTEPS + t + 1) * HDIM + h];
                xt1 = g_xin[((size_t)r1 * TSTEPS + t + 1) * HDIM + h];
            }

            b1_0 = __fadd_rn(__fmul_rn(r1d, b1_0), __fmul_rn(om_r1d, s1reg0));
            b1_1 = __fadd_rn(__fmul_rn(r1d, b1_1), __fmul_rn(om_r1d, s1reg1));
            float B10 = __fadd_rn(0.01f, __fmul_rn(1.8f, b1_0));
            float B11 = __fadd_rn(0.01f, __fmul_rn(1.8f, b1_1));
            h1m0 = __fsub_rn(__fadd_rn(__fmul_rn(h1m0, a1), __fmul_rn(om_a1, i10)),
                             __fmul_rn(B10, s1reg0));
            h1m1 = __fsub_rn(__fadd_rn(__fmul_rn(h1m1, a1), __fmul_rn(om_a1, i11)),
                             __fmul_rn(B11, s1reg1));
            float ns0 = __fsub_rn(h1m0, B10) > 0.f ? 1.f : 0.f;
            float ns1 = __fsub_rn(h1m1, B11) > 0.f ? 1.f : 0.f;
            s1c0 += ns0; s1c1 += ns1;

            s1b[wr + h] = ns0; s1b[wr + HDIM + h] = ns1;
            s1reg0 = ns0; s1reg1 = ns1;
            BARSYNC(1, 128);                     // new s1 visible (compute only)

            // ---- dot12 over NEW s1 ----
            float d12_0 = 0.f, d12_1 = 0.f;
            dot_pair(w12, s1b + wr, s1b + wr + HDIM, h, d12_0, d12_1);
            // i2 = ((dot12 + b12) + dot22) + b22   (reference association)
            float i20 = __fadd_rn(__fadd_rn(__fadd_rn(d12_0, b12), d22_0), b22c);
            float i21 = __fadd_rn(__fadd_rn(__fadd_rn(d12_1, b12), d22_1), b22c);

            b2_0 = __fadd_rn(__fmul_rn(r2d, b2_0), __fmul_rn(om_r2d, s2reg0));
            b2_1 = __fadd_rn(__fmul_rn(r2d, b2_1), __fmul_rn(om_r2d, s2reg1));
            float B20 = __fadd_rn(0.01f, __fmul_rn(1.8f, b2_0));
            float B21 = __fadd_rn(0.01f, __fmul_rn(1.8f, b2_1));
            h2m0 = __fsub_rn(__fadd_rn(__fmul_rn(h2m0, a2), __fmul_rn(om_a2, i20)),
                             __fmul_rn(B20, s2reg0));
            h2m1 = __fsub_rn(__fadd_rn(__fmul_rn(h2m1, a2), __fmul_rn(om_a2, i21)),
                             __fmul_rn(B21, s2reg1));
            float ms0 = __fsub_rn(h2m0, B20) > 0.f ? 1.f : 0.f;
            float ms1 = __fsub_rn(h2m1, B21) > 0.f ? 1.f : 0.f;
            s2c0 += ms0; s2c1 += ms1;

            s2b[wr + h] = ms0; s2b[wr + HDIM + h] = ms1;
            s2reg0 = ms0; s2reg1 = ms1;
            BARSYNC(2, 192);                     // step end: hand s2 to readout
        }

        out[BATCH * ODIM + r0 * HDIM + h] = __fdiv_rn(s1c0, (float)TSTEPS);
        out[BATCH * ODIM + r1 * HDIM + h] = __fdiv_rn(s1c1, (float)TSTEPS);
        out[BATCH * ODIM + BATCH * HDIM + r0 * HDIM + h] = __fdiv_rn(s2c0, (float)TSTEPS);
        out[BATCH * ODIM + BATCH * HDIM + r1 * HDIM + h] = __fdiv_rn(s2c1, (float)TSTEPS);
    } else {
        // ================= readout warps (4-5), one per row =================
        const int lane = tid & 31;
        const int row  = (tid >> 5) - 4;         // 0 or 1

        float om = 0.f, accv = 0.f, ao = 0.f, om_ao = 0.f, b2o = 0.f;
        if (lane < ODIM) {
            om    = out_mem0[(r0 + row) * ODIM + lane];
            ao    = expd(__fdiv_rn(-1.0f, tau_m_o[lane]));
            om_ao = __fsub_rn(1.0f, ao);
            b2o   = b_h2o[lane];
        }
        __syncthreads();

        for (int t = 0; t < TSTEPS; t++) {
            BARSYNC(2, 192);                     // s2 of step t is ready
            const int wr = ((t & 1) ^ 1) * 2 * HDIM;
            const float* ss = s2b + wr + row * HDIM;

            if (lane < ODIM) {
                float dio = 0.f;                 // ascending j, single acc
#pragma unroll 4
                for (int j = 0; j < HDIM; j++)
                    dio = fmaf(ss[j], w2o[j * ODIM + lane], dio);
                float io = __fadd_rn(dio, b2o);
                om = __fadd_rn(__fmul_rn(om, ao), __fmul_rn(om_ao, io));
            }
            // softmax over 20 logits: tree max (exact) + tree sum + expf
            // (feeds only output 0; ulp-level noise, no trajectory feedback)
            float v = (lane < ODIM) ? om : -3.4e38f;
#pragma unroll
            for (int off = 16; off > 0; off >>= 1)
                v = fmaxf(v, __shfl_xor_sync(0xffffffffu, v, off));
            float p = (lane < ODIM) ? expf(__fsub_rn(om, v)) : 0.f;
            float ssum = p;
#pragma unroll
            for (int off = 16; off > 0; off >>= 1)
                ssum = __fadd_rn(ssum, __shfl_xor_sync(0xffffffffu, ssum, off));
            if (lane < ODIM && t > 10)
                accv = __fadd_rn(accv, __fdiv_rn(p, ssum));
        }

        if (lane < ODIM)
            out[(r0 + row) * ODIM + lane] = accv;
    }
}

// ---------------------------------------------------------------------------
extern "C" void kernel_launch(void* const* d_in, const int* in_sizes, int n_in,
                              void* d_out, int out_size)
{
    const float* x         = (const float*)d_in[0];
    const float* mask      = (const float*)d_in[1];
    const float* w_ih1     = (const float*)d_in[2];
    const float* b_ih1     = (const float*)d_in[3];
    const float* w_h1h1    = (const float*)d_in[4];
    const float* b_h1h1    = (const float*)d_in[5];
    const float* w_h1h2    = (const float*)d_in[6];
    const float* b_h1h2    = (const float*)d_in[7];
    const float* w_h2h2    = (const float*)d_in[8];
    const float* b_h2h2    = (const float*)d_in[9];
    const float* w_h2o     = (const float*)d_in[10];
    const float* b_h2o     = (const float*)d_in[11];
    const float* tau_adp_h1= (const float*)d_in[12];
    const float* tau_adp_h2= (const float*)d_in[13];
    const float* tau_m_h1  = (const float*)d_in[14];
    const float* tau_m_h2  = (const float*)d_in[15];
    const float* tau_m_o   = (const float*)d_in[16];
    const float* hid1_mem0 = (const float*)d_in[17];
    const float* hid2_mem0 = (const float*)d_in[18];
    const float* out_mem0  = (const float*)d_in[19];
    float* out = (float*)d_out;

    gemm_xin_kernel<<<(BATCH * TSTEPS) / BM, 256>>>(x, w_ih1, b_ih1);

    anorm_kernel<<<1, 256>>>(w_h1h1, w_h2h2, mask, out);

    size_t smem = SMEM_FLOATS * sizeof(float);
    cudaFuncSetAttribute(scan_kernel,
                         cudaFuncAttributeMaxDynamicSharedMemorySize,
                         (int)smem);
    scan_kernel<<<BATCH / 2, NTHREADS_SCAN, smem>>>(
        mask, w_h1h1, b_h1h1, w_h1h2, b_h1h2, w_h2h2, b_h2h2,
        w_h2o, b_h2o, tau_adp_h1, tau_adp_h2, tau_m_h1, tau_m_h2,
        tau_m_o, hid1_mem0, hid2_mem0, out_mem0, out);
}

// round 13
// speedup vs baseline: 1.8772x; 1.1308x over previous
#include <cuda_runtime.h>
#include <cuda_bf16.h>
#include <math.h>
#include <stdint.h>

// Problem dims
#define BATCH 256
#define TSTEPS 250
#define IDIM 700
#define HDIM 128
#define ODIM 20

// xin buffer: [B][T][H] fp32 = 32.77 MB
__device__ float g_xin[BATCH * TSTEPS * HDIM];

// Correctly-rounded float exp via double (matches glibc expf). Init-path only.
__device__ __forceinline__ float expd(float x)
{
    return (float)exp((double)x);
}

#define BARSYNC(id, cnt) asm volatile("bar.sync %0, %1;" :: "r"(id), "r"(cnt) : "memory")

// ---------------------------------------------------------------------------
// Kernel 1: xin[m][h] = (sum_k x[m][k]*w[k][h]) + b[h].
// 128x128 tile, 8x8 per thread, BK=16, double-buffered smem.
// Per output element: single fp32 accumulator, strictly ascending k, fmaf,
// zero-padded K tail, bias added once at the end -> bit-identical to R9.
// ---------------------------------------------------------------------------
#define BM 128
#define BN 128
#define BK 16

__global__ __launch_bounds__(256, 2) void gemm_xin_kernel(
    const float* __restrict__ X, const float* __restrict__ W,
    const float* __restrict__ bias)
{
    __shared__ float Xs[2][BK][BM];   // 2 x 8KB (transposed: [k][m])
    __shared__ float Ws[2][BK][BN];   // 2 x 8KB

    const int tid = threadIdx.x;
    const int m0 = blockIdx.x * BM;

    const int tx = tid & 15;          // 0..15
    const int ty = tid >> 4;          // 0..15
    const int mBase = ty * 8;
    const int nBase = tx * 8;

    float acc[8][8];
#pragma unroll
    for (int i = 0; i < 8; i++)
#pragma unroll
        for (int j = 0; j < 8; j++) acc[i][j] = 0.f;

    // X loader: thread -> row lrx (0..127), k-chunk lcx (0 or 8)
    const int lrx = tid & 127;
    const int lcx = (tid >> 7) * 8;
    // W loader: thread -> k-row wrk (0..15), col chunk wck (0..120)
    const int wrk = tid >> 4;
    const int wck = (tid & 15) * 8;

    const int NT = (IDIM + BK - 1) / BK;   // 44

    // prologue: tile 0
#pragma unroll
    for (int i = 0; i < 8; i++) {
        int k = lcx + i;
        Xs[0][lcx + i][lrx] = (k < IDIM) ? X[(size_t)(m0 + lrx) * IDIM + k] : 0.f;
    }
#pragma unroll
    for (int i = 0; i < 8; i++) {
        int k = wrk;
        Ws[0][wrk][wck + i] = (k < IDIM) ? W[(size_t)k * HDIM + wck + i] : 0.f;
    }
    __syncthreads();

    int buf = 0;
    for (int kt = 0; kt < NT; kt++) {
        const bool has_next = (kt + 1) < NT;
        const int k0n = (kt + 1) * BK;

        // stage next tile in registers
        float xr[8], wvr[8];
        if (has_next) {
#pragma unroll
            for (int i = 0; i < 8; i++) {
                int k = k0n + lcx + i;
                xr[i] = (k < IDIM) ? X[(size_t)(m0 + lrx) * IDIM + k] : 0.f;
            }
            int k = k0n + wrk;
#pragma unroll
            for (int i = 0; i < 8; i++)
                wvr[i] = (k < IDIM) ? W[(size_t)k * HDIM + wck + i] : 0.f;
        }

        // compute on current buffer (strictly ascending k)
#pragma unroll
        for (int k = 0; k < BK; k++) {
            float4 x0 = *(float4*)&Xs[buf][k][mBase];
            float4 x1 = *(float4*)&Xs[buf][k][mBase + 4];
            float4 w0 = *(float4*)&Ws[buf][k][nBase];
            float4 w1 = *(float4*)&Ws[buf][k][nBase + 4];
            float xv[8] = {x0.x, x0.y, x0.z, x0.w, x1.x, x1.y, x1.z, x1.w};
            float wv[8] = {w0.x, w0.y, w0.z, w0.w, w1.x, w1.y, w1.z, w1.w};
#pragma unroll
            for (int i = 0; i < 8; i++)
#pragma unroll
                for (int j = 0; j < 8; j++)
                    acc[i][j] = fmaf(xv[i], wv[j], acc[i][j]);
        }

        if (has_next) {
            int nb = buf ^ 1;
#pragma unroll
            for (int i = 0; i < 8; i++) Xs[nb][lcx + i][lrx] = xr[i];
#pragma unroll
            for (int i = 0; i < 8; i++) Ws[nb][wrk][wck + i] = wvr[i];
            __syncthreads();
            buf = nb;
        }
    }

    float4 bb0 = *(const float4*)&bias[nBase];
    float4 bb1 = *(const float4*)&bias[nBase + 4];
#pragma unroll
    for (int i = 0; i < 8; i++) {
        float4 r0, r1;
        r0.x = __fadd_rn(acc[i][0], bb0.x);
        r0.y = __fadd_rn(acc[i][1], bb0.y);
        r0.z = __fadd_rn(acc[i][2], bb0.z);
        r0.w = __fadd_rn(acc[i][3], bb0.w);
        r1.x = __fadd_rn(acc[i][4], bb1.x);
        r1.y = __fadd_rn(acc[i][5], bb1.y);
        r1.z = __fadd_rn(acc[i][6], bb1.z);
        r1.w = __fadd_rn(acc[i][7], bb1.w);
        *(float4*)&g_xin[(size_t)(m0 + mBase + i) * HDIM + nBase] = r0;
        *(float4*)&g_xin[(size_t)(m0 + mBase + i) * HDIM + nBase + 4] = r1;
    }
}

// ---------------------------------------------------------------------------
// Kernel 2: A_norm
// ---------------------------------------------------------------------------
__global__ void anorm_kernel(const float* __restrict__ w11,
                             const float* __restrict__ w22,
                             const float* __restrict__ mask,
                             float* __restrict__ out)
{
    __shared__ float redA[256];
    __shared__ float redB[256];
    int tid = threadIdx.x;
    float sa = 0.f, sb = 0.f;
    for (int i = tid; i < HDIM * HDIM; i += 256) {
        sa += fabsf(__fmul_rn(w11[i], mask[i]));
        sb += fabsf(__fmul_rn(w22[i], mask[HDIM * HDIM + i]));
    }
    redA[tid] = sa;
    redB[tid] = sb;
    __syncthreads();
    for (int o = 128; o > 0; o >>= 1) {
        if (tid < o) { redA[tid] += redA[tid + o]; redB[tid] += redB[tid + o]; }
        __syncthreads();
    }
    if (tid == 0)
        out[BATCH * ODIM + 2 * BATCH * HDIM] = __fadd_rn(redA[0], redB[0]);
}

// ---------------------------------------------------------------------------
// Kernel 3: persistent scan — EXACT R7/R9 version (695us known-good).
// grid = 128 blocks x 192 threads. Warps 0-3: neuron compute. Warps 4-5:
// pipelined readout one step behind on double-buffered s2 arrays.
// ---------------------------------------------------------------------------
__device__ __forceinline__ void dot_pair(const float* __restrict__ W,
                                         const float* __restrict__ sa,
                                         const float* __restrict__ sb,
                                         int h, float& a0, float& a1)
{
#pragma unroll 8
    for (int j = 0; j < HDIM; j += 4) {
        float4 va = *(const float4*)(sa + j);
        float4 vb = *(const float4*)(sb + j);
        float w0 = W[(j + 0) * HDIM + h];
        float w1 = W[(j + 1) * HDIM + h];
        float w2 = W[(j + 2) * HDIM + h];
        float w3 = W[(j + 3) * HDIM + h];
        a0 = fmaf(va.x, w0, a0); a1 = fmaf(vb.x, w0, a1);
        a0 = fmaf(va.y, w1, a0); a1 = fmaf(vb.y, w1, a1);
        a0 = fmaf(va.z, w2, a0); a1 = fmaf(vb.z, w2, a1);
        a0 = fmaf(va.w, w3, a0); a1 = fmaf(vb.w, w3, a1);
    }
}

#define SM_W11 0
#define SM_W12 (HDIM * HDIM)
#define SM_W22 (2 * HDIM * HDIM)
#define SM_W2O (3 * HDIM * HDIM)
#define SM_S1  (3 * HDIM * HDIM + HDIM * ODIM)   // [2 phase][2 row][128]
#define SM_S2  (SM_S1 + 4 * HDIM)
#define SMEM_FLOATS (SM_S2 + 4 * HDIM)

#define NTHREADS_SCAN 192

__global__ __launch_bounds__(NTHREADS_SCAN) void scan_kernel(
    const float* __restrict__ mask,
    const float* __restrict__ w_h1h1, const float* __restrict__ b_h1h1,
    const float* __restrict__ w_h1h2, const float* __restrict__ b_h1h2,
    const float* __restrict__ w_h2h2, const float* __restrict__ b_h2h2,
    const float* __restrict__ w_h2o,  const float* __restrict__ b_h2o,
    const float* __restrict__ tau_adp_h1, const float* __restrict__ tau_adp_h2,
    const float* __restrict__ tau_m_h1,   const float* __restrict__ tau_m_h2,
    const float* __restrict__ tau_m_o,
    const float* __restrict__ hid1_mem0, const float* __restrict__ hid2_mem0,
    const float* __restrict__ out_mem0,
    float* __restrict__ out)
{
    extern __shared__ float sm[];
    float* w11 = sm + SM_W11;
    float* w12 = sm + SM_W12;
    float* w22 = sm + SM_W22;
    float* w2o = sm + SM_W2O;
    float* s1b = sm + SM_S1;   // [phase][row][128]
    float* s2b = sm + SM_S2;

    const int tid = threadIdx.x;
    const int r0 = blockIdx.x * 2;
    const int r1 = r0 + 1;

    for (int idx = tid; idx < HDIM * HDIM; idx += NTHREADS_SCAN) {
        w11[idx] = __fmul_rn(w_h1h1[idx], mask[idx]);
        w12[idx] = w_h1h2[idx];
        w22[idx] = __fmul_rn(w_h2h2[idx], mask[HDIM * HDIM + idx]);
    }
    for (int idx = tid; idx < HDIM * ODIM; idx += NTHREADS_SCAN)
        w2o[idx] = w_h2o[idx];

    if (tid < 128) {
        // ================= compute warps (0-3) =================
        const int h = tid;

        const float a1  = expd(__fdiv_rn(-1.0f, tau_m_h1[h]));
        const float r1d = expd(__fdiv_rn(-1.0f, tau_adp_h1[h]));
        const float a2  = expd(__fdiv_rn(-1.0f, tau_m_h2[h]));
        const float r2d = expd(__fdiv_rn(-1.0f, tau_adp_h2[h]));
        const float om_a1  = __fsub_rn(1.0f, a1);
        const float om_r1d = __fsub_rn(1.0f, r1d);
        const float om_a2  = __fsub_rn(1.0f, a2);
        const float om_r2d = __fsub_rn(1.0f, r2d);
        const float bh11 = b_h1h1[h];
        const float b12  = b_h1h2[h];
        const float b22c = b_h2h2[h];

        float h1m0 = hid1_mem0[r0 * HDIM + h], h1m1 = hid1_mem0[r1 * HDIM + h];
        float h2m0 = hid2_mem0[r0 * HDIM + h], h2m1 = hid2_mem0[r1 * HDIM + h];
        float b1_0 = 0.01f, b1_1 = 0.01f, b2_0 = 0.01f, b2_1 = 0.01f;
        float s1reg0 = 0.f, s1reg1 = 0.f, s2reg0 = 0.f, s2reg1 = 0.f;
        float s1c0 = 0.f, s1c1 = 0.f, s2c0 = 0.f, s2c1 = 0.f;

        // zero phase-0 spike buffers (read at t=0)
        s1b[h] = 0.f; s1b[HDIM + h] = 0.f;
        s2b[h] = 0.f; s2b[HDIM + h] = 0.f;

        __syncthreads();

        float xt0 = g_xin[((size_t)r0 * TSTEPS + 0) * HDIM + h];
        float xt1 = g_xin[((size_t)r1 * TSTEPS + 0) * HDIM + h];

        for (int t = 0; t < TSTEPS; t++) {
            const int rd = (t & 1) * 2 * HDIM;
            const int wr = ((t & 1) ^ 1) * 2 * HDIM;

            // ---- layer 1 ----
            float d11_0 = 0.f, d11_1 = 0.f;
            dot_pair(w11, s1b + rd, s1b + rd + HDIM, h, d11_0, d11_1);
            float i10 = __fadd_rn(__fadd_rn(xt0, d11_0), bh11);
            float i11 = __fadd_rn(__fadd_rn(xt1, d11_1), bh11);
            if (t < TSTEPS - 1) {
                xt0 = g_xin[((size_t)r0 * TSTEPS + t + 1) * HDIM + h];
                xt1 = g_xin[((size_t)r1 * TSTEPS + t + 1) * HDIM + h];
            }

            b1_0 = __fadd_rn(__fmul_rn(r1d, b1_0), __fmul_rn(om_r1d, s1reg0));
            b1_1 = __fadd_rn(__fmul_rn(r1d, b1_1), __fmul_rn(om_r1d, s1reg1));
            float B10 = __fadd_rn(0.01f, __fmul_rn(1.8f, b1_0));
            float B11 = __fadd_rn(0.01f, __fmul_rn(1.8f, b1_1));
            h1m0 = __fsub_rn(__fadd_rn(__fmul_rn(h1m0, a1), __fmul_rn(om_a1, i10)),
                             __fmul_rn(B10, s1reg0));
            h1m1 = __fsub_rn(__fadd_rn(__fmul_rn(h1m1, a1), __fmul_rn(om_a1, i11)),
                             __fmul_rn(B11, s1reg1));
            float ns0 = __fsub_rn(h1m0, B10) > 0.f ? 1.f : 0.f;
            float ns1 = __fsub_rn(h1m1, B11) > 0.f ? 1.f : 0.f;
            s1c0 += ns0; s1c1 += ns1;

            s1b[wr + h] = ns0; s1b[wr + HDIM + h] = ns1;
            s1reg0 = ns0; s1reg1 = ns1;
            BARSYNC(1, 128);                     // new s1 visible (compute only)

            // ---- layer 2 ----
            float d12_0 = 0.f, d12_1 = 0.f;
            dot_pair(w12, s1b + wr, s1b + wr + HDIM, h, d12_0, d12_1);
            float d22_0 = 0.f, d22_1 = 0.f;
            dot_pair(w22, s2b + rd, s2b + rd + HDIM, h, d22_0, d22_1);
            float i20 = __fadd_rn(__fadd_rn(__fadd_rn(d12_0, b12), d22_0), b22c);
            float i21 = __fadd_rn(__fadd_rn(__fadd_rn(d12_1, b12), d22_1), b22c);

            b2_0 = __fadd_rn(__fmul_rn(r2d, b2_0), __fmul_rn(om_r2d, s2reg0));
            b2_1 = __fadd_rn(__fmul_rn(r2d, b2_1), __fmul_rn(om_r2d, s2reg1));
            float B20 = __fadd_rn(0.01f, __fmul_rn(1.8f, b2_0));
            float B21 = __fadd_rn(0.01f, __fmul_rn(1.8f, b2_1));
            h2m0 = __fsub_rn(__fadd_rn(__fmul_rn(h2m0, a2), __fmul_rn(om_a2, i20)),
                             __fmul_rn(B20, s2reg0));
            h2m1 = __fsub_rn(__fadd_rn(__fmul_rn(h2m1, a2), __fmul_rn(om_a2, i21)),
                             __fmul_rn(B21, s2reg1));
            float ms0 = __fsub_rn(h2m0, B20) > 0.f ? 1.f : 0.f;
            float ms1 = __fsub_rn(h2m1, B21) > 0.f ? 1.f : 0.f;
            s2c0 += ms0; s2c1 += ms1;

            s2b[wr + h] = ms0; s2b[wr + HDIM + h] = ms1;
            s2reg0 = ms0; s2reg1 = ms1;
            BARSYNC(2, 192);                     // step end: hand s2 to readout
        }

        out[BATCH * ODIM + r0 * HDIM + h] = __fdiv_rn(s1c0, (float)TSTEPS);
        out[BATCH * ODIM + r1 * HDIM + h] = __fdiv_rn(s1c1, (float)TSTEPS);
        out[BATCH * ODIM + BATCH * HDIM + r0 * HDIM + h] = __fdiv_rn(s2c0, (float)TSTEPS);
        out[BATCH * ODIM + BATCH * HDIM + r1 * HDIM + h] = __fdiv_rn(s2c1, (float)TSTEPS);
    } else {
        // ================= readout warps (4-5), one per row =================
        const int lane = tid & 31;
        const int row  = (tid >> 5) - 4;         // 0 or 1

        float om = 0.f, accv = 0.f, ao = 0.f, om_ao = 0.f, b2o = 0.f;
        if (lane < ODIM) {
            om    = out_mem0[(r0 + row) * ODIM + lane];
            ao    = expd(__fdiv_rn(-1.0f, tau_m_o[lane]));
            om_ao = __fsub_rn(1.0f, ao);
            b2o   = b_h2o[lane];
        }
        __syncthreads();

        for (int t = 0; t < TSTEPS; t++) {
            BARSYNC(2, 192);                     // s2 of step t is ready
            const int wr = ((t & 1) ^ 1) * 2 * HDIM;
            const float* ss = s2b + wr + row * HDIM;

            if (lane < ODIM) {
                float dio = 0.f;                 // ascending j, single acc
#pragma unroll 4
                for (int j = 0; j < HDIM; j++)
                    dio = fmaf(ss[j], w2o[j * ODIM + lane], dio);
                float io = __fadd_rn(dio, b2o);
                om = __fadd_rn(__fmul_rn(om, ao), __fmul_rn(om_ao, io));
            }
            // softmax over 20 logits: tree max (exact) + tree sum + expf
            // (feeds only output 0; ulp-level noise, no trajectory feedback)
            float v = (lane < ODIM) ? om : -3.4e38f;
#pragma unroll
            for (int off = 16; off > 0; off >>= 1)
                v = fmaxf(v, __shfl_xor_sync(0xffffffffu, v, off));
            float p = (lane < ODIM) ? expf(__fsub_rn(om, v)) : 0.f;
            float ssum = p;
#pragma unroll
            for (int off = 16; off > 0; off >>= 1)
                ssum = __fadd_rn(ssum, __shfl_xor_sync(0xffffffffu, ssum, off));
            if (lane < ODIM && t > 10)
                accv = __fadd_rn(accv, __fdiv_rn(p, ssum));
        }

        if (lane < ODIM)
            out[(r0 + row) * ODIM + lane] = accv;
    }
}

// ---------------------------------------------------------------------------
extern "C" void kernel_launch(void* const* d_in, const int* in_sizes, int n_in,
                              void* d_out, int out_size)
{
    const float* x         = (const float*)d_in[0];
    const float* mask      = (const float*)d_in[1];
    const float* w_ih1     = (const float*)d_in[2];
    const float* b_ih1     = (const float*)d_in[3];
    const float* w_h1h1    = (const float*)d_in[4];
    const float* b_h1h1    = (const float*)d_in[5];
    const float* w_h1h2    = (const float*)d_in[6];
    const float* b_h1h2    = (const float*)d_in[7];
    const float* w_h2h2    = (const float*)d_in[8];
    const float* b_h2h2    = (const float*)d_in[9];
    const float* w_h2o     = (const float*)d_in[10];
    const float* b_h2o     = (const float*)d_in[11];
    const float* tau_adp_h1= (const float*)d_in[12];
    const float* tau_adp_h2= (const float*)d_in[13];
    const float* tau_m_h1  = (const float*)d_in[14];
    const float* tau_m_h2  = (const float*)d_in[15];
    const float* tau_m_o   = (const float*)d_in[16];
    const float* hid1_mem0 = (const float*)d_in[17];
    const float* hid2_mem0 = (const float*)d_in[18];
    const float* out_mem0  = (const float*)d_in[19];
    float* out = (float*)d_out;

    gemm_xin_kernel<<<(BATCH * TSTEPS) / BM, 256>>>(x, w_ih1, b_ih1);

    anorm_kernel<<<1, 256>>>(w_h1h1, w_h2h2, mask, out);

    size_t smem = SMEM_FLOATS * sizeof(float);
    cudaFuncSetAttribute(scan_kernel,
                         cudaFuncAttributeMaxDynamicSharedMemorySize,
                         (int)smem);
    scan_kernel<<<BATCH / 2, NTHREADS_SCAN, smem>>>(
        mask, w_h1h1, b_h1h1, w_h1h2, b_h1h2, w_h2h2, b_h2h2,
        w_h2o, b_h2o, tau_adp_h1, tau_adp_h2, tau_m_h1, tau_m_h2,
        tau_m_o, hid1_mem0, hid2_mem0, out_mem0, out);
}